// round 16
// baseline (speedup 1.0000x reference)
#include <cuda_runtime.h>
#include <cuda_bf16.h>
#include <math.h>

// HMM forward, linear domain, power-of-2 rescale. 32 clusters x 4 CTAs,
// 2 batches/cluster. R15: 8 warps/CTA, each warp = one m16 row tile x FULL
// K=512 (Areg = 128 regs/thread, 32 MMAs as 4x8 chains) -> z complete in
// registers, NO intra-CTA reduction or post-MMA barrier. Epilogue in tig==0
// lanes. DSMEM pair-push transport + count-4 arrives (R13-proven).

#define HH 512
#define VV 50257
#define TT 512
#define NT 256
#define RPC 128
#define NCL 32

using ull = unsigned long long;
using u32 = unsigned int;

#define CLUSTER_SYNC() do { \
  asm volatile("barrier.cluster.arrive.aligned;" ::: "memory"); \
  asm volatile("barrier.cluster.wait.aligned;"   ::: "memory"); \
} while (0)

__device__ __forceinline__ u32 smem_u32(const void* p) {
  u32 a;
  asm("{ .reg .u64 t; cvta.to.shared.u64 t, %1; cvt.u32.u64 %0, t; }" : "=r"(a) : "l"(p));
  return a;
}
__device__ __forceinline__ u32 mapa_u32(u32 local, int rank) {
  u32 r;
  asm("mapa.shared::cluster.u32 %0, %1, %2;" : "=r"(r) : "r"(local), "r"(rank));
  return r;
}
__device__ __forceinline__ void mbar_wait_acq(u32 addr, u32 ph) {
  asm volatile(
    "{\n\t.reg .pred P;\n\t"
    "W%=:\n\t"
    "mbarrier.try_wait.parity.acquire.cluster.shared::cta.b64 P, [%0], %1, 0x989680;\n\t"
    "@!P bra W%=;\n\t}"
    :: "r"(addr), "r"(ph) : "memory");
}
__device__ __forceinline__ u32 pkbf(float a, float b) {
  __nv_bfloat162 t = __float22bfloat162_rn(make_float2(a, b));
  return *(u32*)&t;
}
#define MMA16816(c0, c1, c2, c3, a0, a1, a2, a3, b0, b1) \
  asm volatile( \
    "mma.sync.aligned.m16n8k16.row.col.f32.bf16.bf16.f32 " \
    "{%0,%1,%2,%3}, {%4,%5,%6,%7}, {%8,%9}, {%0,%1,%2,%3};" \
    : "+f"(c0), "+f"(c1), "+f"(c2), "+f"(c3) \
    : "r"(a0), "r"(a1), "r"(a2), "r"(a3), "r"(b0), "r"(b1))

__global__ void __cluster_dims__(4, 1, 1) __launch_bounds__(NT, 1)
hmm_main(const float* __restrict__ A, const float* __restrict__ beta,
         const float* __restrict__ gamma, const int* __restrict__ ids,
         float* __restrict__ out) {
  __shared__ __align__(16) u32   xsb[2][2][264];  // [par][b][kp] bf16x2, pad
  __shared__ __align__(16) float wmx[2][2][32];   // [par][b][slice*8 + mt]
  __shared__ __align__(16) float a0s[1024];
  __shared__ int   sids[2][TT];
  __shared__ float smax2[8];
  __shared__ __align__(8) ull mbars2[2];          // per-parity, count=4

  const int tid  = threadIdx.x;
  const int myq  = blockIdx.x & 3;     // cluster rank == row-slice
  const int cl   = blockIdx.x >> 2;    // cluster id
  const int base = myq * RPC;
  const int warp = tid >> 5, lane = tid & 31;
  const int mt = warp;                 // m-tile of this warp (full K)
  const int r4 = lane >> 2, tig = lane & 3;

  // ---- prologue: full-K W fragments into registers (128 u32/thread) ----
  u32 Areg[128];
  {
    const int row0 = base + mt * 16 + r4;
    #pragma unroll
    for (int kt = 0; kt < 32; kt++) {
      const int k0 = kt * 16 + 2 * tig;
      const float* p0 = A + (size_t)k0 * HH;
      float w00 = p0[row0]              + 1e-12f;
      float w01 = p0[HH + row0]         + 1e-12f;
      float w10 = p0[row0 + 8]          + 1e-12f;
      float w11 = p0[HH + row0 + 8]     + 1e-12f;
      float w20 = p0[8 * HH + row0]     + 1e-12f;
      float w21 = p0[9 * HH + row0]     + 1e-12f;
      float w30 = p0[8 * HH + row0 + 8] + 1e-12f;
      float w31 = p0[9 * HH + row0 + 8] + 1e-12f;
      Areg[kt * 4 + 0] = pkbf(w00, w01);
      Areg[kt * 4 + 1] = pkbf(w10, w11);
      Areg[kt * 4 + 2] = pkbf(w20, w21);
      Areg[kt * 4 + 3] = pkbf(w30, w31);
    }
  }
  for (int i = tid; i < 2 * TT; i += NT) {
    int b0 = i >> 9, t0 = i & (TT - 1);
    sids[b0][t0] = ids[(cl * 2 + b0) * TT + t0];
  }
  if (tid < 2)
    asm volatile("mbarrier.init.shared.b64 [%0], %1;"
                 :: "r"(smem_u32(&mbars2[tid])), "r"(4u) : "memory");
  __syncthreads();

  // ---- init: alpha0 (2 batches), M0; x1 + wmx[1] built LOCALLY ----
  float M0[2];
  {
    for (int idx = tid; idx < 2 * HH; idx += NT) {
      int bb = idx >> 9, k = idx & 511;
      a0s[idx] = __logf(gamma[k]) + __ldg(&beta[(size_t)k * VV + sids[bb][0]]);
    }
    __syncthreads();
    {
      int bb = warp >> 2, seg = warp & 3;       // 4 warps per batch, 128 each
      float m = a0s[bb * 512 + seg * 128 + lane];
      #pragma unroll
      for (int i = 1; i < 4; i++)
        m = fmaxf(m, a0s[bb * 512 + seg * 128 + i * 32 + lane]);
      #pragma unroll
      for (int o = 16; o > 0; o >>= 1)
        m = fmaxf(m, __shfl_xor_sync(0xffffffffu, m, o));
      if (lane == 0) smax2[warp] = m;
    }
    __syncthreads();
    #pragma unroll
    for (int bb = 0; bb < 2; bb++)
      M0[bb] = fmaxf(fmaxf(smax2[bb * 4], smax2[bb * 4 + 1]),
                     fmaxf(smax2[bb * 4 + 2], smax2[bb * 4 + 3]));
    for (int i = tid; i < 512; i += NT) {
      int bx = i >> 8, kp = i & 255;
      float v0 = __expf(a0s[bx * 512 + 2 * kp]     - M0[bx]);
      float v1 = __expf(a0s[bx * 512 + 2 * kp + 1] - M0[bx]);
      xsb[1][bx][kp] = pkbf(v0, v1);
    }
    if (tid < 64) {
      int q = tid >> 4, mti = (tid >> 1) & 7, bb = tid & 1;
      float m = a0s[bb * 512 + q * 128 + mti * 16];
      #pragma unroll
      for (int i = 1; i < 16; i++)
        m = fmaxf(m, a0s[bb * 512 + q * 128 + mti * 16 + i]);
      wmx[1][bb][q * 8 + mti] = __expf(m - M0[bb]);
    }
    __syncthreads();
  }
  CLUSTER_SYNC();

  const bool epi = (tig == 0);
  const int  h0  = base + mt * 16 + r4;   // epi rows: h0 and h0+8
  const int  h8  = h0 + 8;
  int Ce0 = 0, Ce1 = 0;
  const u32 xsb_u = smem_u32(xsb);
  const u32 wmx_u = smem_u32(wmx);
  const u32 mb0_u = smem_u32(&mbars2[0]);
  int phs0 = 0, phs1 = 0;

  // depth-2 emission prefetch (4 streams per epi thread)
  float e00 = 0.f, e01 = 0.f, e80 = 0.f, e81 = 0.f;
  float q00 = 0.f, q01 = 0.f, q80 = 0.f, q81 = 0.f;
  if (epi) {
    e00 = __expf(__ldg(&beta[(size_t)h0 * VV + sids[0][1]]));
    e01 = __expf(__ldg(&beta[(size_t)h0 * VV + sids[1][1]]));
    e80 = __expf(__ldg(&beta[(size_t)h8 * VV + sids[0][1]]));
    e81 = __expf(__ldg(&beta[(size_t)h8 * VV + sids[1][1]]));
    q00 = __ldg(&beta[(size_t)h0 * VV + sids[0][2]]);
    q01 = __ldg(&beta[(size_t)h0 * VV + sids[1][2]]);
    q80 = __ldg(&beta[(size_t)h8 * VV + sids[0][2]]);
    q81 = __ldg(&beta[(size_t)h8 * VV + sids[1][2]]);
  }

  for (int t = 1; t < TT; t++) {
    const int par = t & 1;

    float n00 = 0.f, n01 = 0.f, n80 = 0.f, n81 = 0.f;
    if (epi && t + 2 < TT) {
      n00 = __ldg(&beta[(size_t)h0 * VV + sids[0][t + 2]]);
      n01 = __ldg(&beta[(size_t)h0 * VV + sids[1][t + 2]]);
      n80 = __ldg(&beta[(size_t)h8 * VV + sids[0][t + 2]]);
      n81 = __ldg(&beta[(size_t)h8 * VV + sids[1][t + 2]]);
    }

    if (t >= 2) {
      if (par == 0) { mbar_wait_acq(mb0_u, phs0); phs0 ^= 1; }
      else          { mbar_wait_acq(mb0_u + 8, phs1); phs1 ^= 1; }
    }

    // M-fold (hidden under MMA): tig-distributed, 8 values each, shfl-combine
    float m0 = wmx[par][0][tig * 8], m1 = wmx[par][1][tig * 8];
    #pragma unroll
    for (int j = 1; j < 8; j++) {
      m0 = fmaxf(m0, wmx[par][0][tig * 8 + j]);
      m1 = fmaxf(m1, wmx[par][1][tig * 8 + j]);
    }
    m0 = fmaxf(m0, __shfl_xor_sync(0xffffffffu, m0, 1));
    m0 = fmaxf(m0, __shfl_xor_sync(0xffffffffu, m0, 2));
    m1 = fmaxf(m1, __shfl_xor_sync(0xffffffffu, m1, 1));
    m1 = fmaxf(m1, __shfl_xor_sync(0xffffffffu, m1, 2));
    const int eb0 = (int)(__float_as_uint(m0) >> 23);
    const int eb1 = (int)(__float_as_uint(m1) >> 23);
    const float i0 = __uint_as_float((u32)(254 - eb0) << 23);
    const float i1 = __uint_as_float((u32)(254 - eb1) << 23);

    // 32 MMAs: 4 interleaved chains of 8; z complete in registers
    float ac[16];
    #pragma unroll
    for (int i = 0; i < 16; i++) ac[i] = 0.f;
    #pragma unroll
    for (int j = 0; j < 8; j++) {
      #pragma unroll
      for (int c = 0; c < 4; c++) {
        const int kt = c * 8 + j;
        u32 b0 = 0, b1 = 0;
        if (lane < 8) {
          b0 = xsb[par][r4][kt * 8 + tig];
          b1 = xsb[par][r4][kt * 8 + tig + 4];
        }
        MMA16816(ac[c * 4 + 0], ac[c * 4 + 1], ac[c * 4 + 2], ac[c * 4 + 3],
                 Areg[kt * 4 + 0], Areg[kt * 4 + 1],
                 Areg[kt * 4 + 2], Areg[kt * 4 + 3], b0, b1);
      }
    }

    float u00 = 0.f, u01 = 0.f, u80 = 0.f, u81 = 0.f;
    if (epi) {   // tig==0 threads hold cols 0,1 (the two real batches)
      float z0 = (ac[0] + ac[4]) + (ac[8] + ac[12]);
      float z1 = (ac[1] + ac[5]) + (ac[9] + ac[13]);
      float z2 = (ac[2] + ac[6]) + (ac[10] + ac[14]);
      float z3 = (ac[3] + ac[7]) + (ac[11] + ac[15]);
      u00 = z0 * e00 * i0;
      u01 = z1 * e01 * i1;
      u80 = z2 * e80 * i0;
      u81 = z3 * e81 * i1;
      Ce0 += eb0 - 127;
      Ce1 += eb1 - 127;
    }

    if (t == TT - 1) {
      if (epi) {
        const double L2C = 0.6931471805599453;
        out[(cl * 2 + 0) * HH + h0] =
            (float)((double)__logf(u00) + (double)M0[0] + (double)Ce0 * L2C);
        out[(cl * 2 + 1) * HH + h0] =
            (float)((double)__logf(u01) + (double)M0[1] + (double)Ce1 * L2C);
        out[(cl * 2 + 0) * HH + h8] =
            (float)((double)__logf(u80) + (double)M0[0] + (double)Ce0 * L2C);
        out[(cl * 2 + 1) * HH + h8] =
            (float)((double)__logf(u81) + (double)M0[1] + (double)Ce1 * L2C);
      }
    } else {
      // partner exchange (rows h0^1, h8^1 live at lane^4)
      float p00 = __shfl_xor_sync(0xffffffffu, u00, 4);
      float p01 = __shfl_xor_sync(0xffffffffu, u01, 4);
      float p80 = __shfl_xor_sync(0xffffffffu, u80, 4);
      float p81 = __shfl_xor_sync(0xffffffffu, u81, 4);

      u32 wm0u = 0, wm1u = 0;
      if (epi) {
        // pair-packed u32 pushes: even r4 -> batch0 pairs, odd r4 -> batch1
        u32 pairA, pairB, bsel;
        if ((r4 & 1) == 0) { pairA = pkbf(u00, p00); pairB = pkbf(u80, p80); bsel = 0; }
        else               { pairA = pkbf(p01, u01); pairB = pkbf(p81, u81); bsel = 1; }
        u32 offA = xsb_u + (u32)((((par ^ 1) * 2 + bsel) * 264 + (h0 >> 1)) * 4);
        u32 offB = xsb_u + (u32)((((par ^ 1) * 2 + bsel) * 264 + (h8 >> 1)) * 4);
        #pragma unroll
        for (int q = 0; q < 4; q++) {
          u32 raA = mapa_u32(offA, q);
          u32 raB = mapa_u32(offB, q);
          asm volatile("st.shared::cluster.u32 [%0], %1;" :: "r"(raA), "r"(pairA) : "memory");
          asm volatile("st.shared::cluster.u32 [%0], %1;" :: "r"(raB), "r"(pairB) : "memory");
        }
        wm0u = __float_as_uint(fmaxf(u00, u80));
        wm1u = __float_as_uint(fmaxf(u01, u81));
        // refill emission pipeline
        e00 = __expf(q00); e01 = __expf(q01);
        e80 = __expf(q80); e81 = __expf(q81);
        q00 = n00; q01 = n01; q80 = n80; q81 = n81;
      }
      // warp max per batch (u > 0 => float max == uint max)
      asm("redux.sync.max.u32 %0, %1, 0xffffffff;" : "=r"(wm0u) : "r"(wm0u));
      asm("redux.sync.max.u32 %0, %1, 0xffffffff;" : "=r"(wm1u) : "r"(wm1u));
      if (lane < 8) {
        u32 bsel2 = (u32)(lane >> 2);           // lanes 0-3: b0, lanes 4-7: b1
        u32 val = (lane < 4) ? wm0u : wm1u;
        u32 woff = wmx_u + (u32)((((par ^ 1) * 2 + bsel2) * 32 + myq * 8 + mt) * 4);
        u32 wra = mapa_u32(woff, lane & 3);
        asm volatile("st.shared::cluster.u32 [%0], %1;" :: "r"(wra), "r"(val) : "memory");
      }

      __syncthreads();   // all warps' pushes issued; xsb[par] reads done
      if (warp == 0 && lane < 4) {
        u32 ra = mapa_u32(mb0_u + (u32)((par ^ 1) * 8), lane);
        asm volatile("mbarrier.arrive.release.cluster.shared::cluster.b64 _, [%0];"
                     :: "r"(ra) : "memory");
      }
    }
  }
}

extern "C" void kernel_launch(void* const* d_in, const int* in_sizes, int n_in,
                              void* d_out, int out_size) {
  const float* A     = (const float*)d_in[0];   // alpha_exp (H,H)
  const float* beta  = (const float*)d_in[1];   // (H,V)
  const float* gamma = (const float*)d_in[2];   // (1,H)
  const int*   ids   = (const int*)d_in[3];     // (B,T) int32
  float* out = (float*)d_out;                   // (B,H) f32

  hmm_main<<<128, NT>>>(A, beta, gamma, ids, out);
}

// round 17
// speedup vs baseline: 1.6462x; 1.6462x over previous
#include <cuda_runtime.h>
#include <cuda_bf16.h>
#include <math.h>

// HMM forward, linear domain, power-of-2 rescale, HMMA matvec (W in regs),
// DSMEM-push x exchange. 32 clusters x 4 CTAs, 2 batches/cluster.
// R16 = R13 (best: 688us) + M-fold hoisted under MMA latency + redux warp max.
// Transport/barriers byte-identical to R13: pair-packed u32 pushes (2 remote
// stores/act thread), count-4 per-parity mbars, bar.sync(1,256) publish.

#define HH 512
#define VV 50257
#define TT 512
#define NT 512
#define RPC 128
#define NCL 32

using ull = unsigned long long;
using u32 = unsigned int;

#define CLUSTER_SYNC() do { \
  asm volatile("barrier.cluster.arrive.aligned;" ::: "memory"); \
  asm volatile("barrier.cluster.wait.aligned;"   ::: "memory"); \
} while (0)

__device__ __forceinline__ u32 smem_u32(const void* p) {
  u32 a;
  asm("{ .reg .u64 t; cvta.to.shared.u64 t, %1; cvt.u32.u64 %0, t; }" : "=r"(a) : "l"(p));
  return a;
}
__device__ __forceinline__ u32 mapa_u32(u32 local, int rank) {
  u32 r;
  asm("mapa.shared::cluster.u32 %0, %1, %2;" : "=r"(r) : "r"(local), "r"(rank));
  return r;
}
__device__ __forceinline__ void mbar_wait_acq(u32 addr, u32 ph) {
  asm volatile(
    "{\n\t.reg .pred P;\n\t"
    "W%=:\n\t"
    "mbarrier.try_wait.parity.acquire.cluster.shared::cta.b64 P, [%0], %1, 0x989680;\n\t"
    "@!P bra W%=;\n\t}"
    :: "r"(addr), "r"(ph) : "memory");
}
__device__ __forceinline__ u32 pkbf(float a, float b) {
  __nv_bfloat162 t = __float22bfloat162_rn(make_float2(a, b));
  return *(u32*)&t;
}
#define MMA16816(c0, c1, c2, c3, a0, a1, a2, a3, b0, b1) \
  asm volatile( \
    "mma.sync.aligned.m16n8k16.row.col.f32.bf16.bf16.f32 " \
    "{%0,%1,%2,%3}, {%4,%5,%6,%7}, {%8,%9}, {%0,%1,%2,%3};" \
    : "+f"(c0), "+f"(c1), "+f"(c2), "+f"(c3) \
    : "r"(a0), "r"(a1), "r"(a2), "r"(a3), "r"(b0), "r"(b1))

__global__ void __cluster_dims__(4, 1, 1) __launch_bounds__(NT, 1)
hmm_main(const float* __restrict__ A, const float* __restrict__ beta,
         const float* __restrict__ gamma, const int* __restrict__ ids,
         float* __restrict__ out) {
  __shared__ __align__(16) u32    xsb[2][2][264];  // [par][b][kp] bf16x2, pad
  __shared__ __align__(16) float2 red2[2][128];    // [khalf][row] = (b0,b1)
  __shared__ float wmxp[2][4][4][2];               // [par][slice][quarter][b]
  __shared__ __align__(16) float a0s[1024];
  __shared__ int   sids[2][TT];
  __shared__ float smax2[16];
  __shared__ __align__(8) ull mbars2[2];           // per-parity, count=4

  const int tid  = threadIdx.x;
  const int myq  = blockIdx.x & 3;     // cluster rank == row-slice
  const int cl   = blockIdx.x >> 2;    // cluster id
  const int base = myq * RPC;
  const int warp = tid >> 5, lane = tid & 31;
  const int mt = warp & 7, kh = warp >> 3;   // m-tile, k-half
  const int r4 = lane >> 2, tig = lane & 3;

  // ---- prologue: W fragments into registers (persistent, 64 u32) ----
  u32 Areg[64];
  {
    const int row0 = base + mt * 16 + r4;
    #pragma unroll
    for (int kt = 0; kt < 16; kt++) {
      const int k0 = kh * 256 + kt * 16 + 2 * tig;
      const float* p0 = A + (size_t)k0 * HH;
      float w00 = p0[row0]              + 1e-12f;
      float w01 = p0[HH + row0]         + 1e-12f;
      float w10 = p0[row0 + 8]          + 1e-12f;
      float w11 = p0[HH + row0 + 8]     + 1e-12f;
      float w20 = p0[8 * HH + row0]     + 1e-12f;
      float w21 = p0[9 * HH + row0]     + 1e-12f;
      float w30 = p0[8 * HH + row0 + 8] + 1e-12f;
      float w31 = p0[9 * HH + row0 + 8] + 1e-12f;
      Areg[kt * 4 + 0] = pkbf(w00, w01);
      Areg[kt * 4 + 1] = pkbf(w10, w11);
      Areg[kt * 4 + 2] = pkbf(w20, w21);
      Areg[kt * 4 + 3] = pkbf(w30, w31);
    }
  }
  for (int i = tid; i < 2 * TT; i += NT) {
    int b0 = i >> 9, t0 = i & (TT - 1);
    sids[b0][t0] = ids[(cl * 2 + b0) * TT + t0];
  }
  if (tid < 2)
    asm volatile("mbarrier.init.shared.b64 [%0], %1;"
                 :: "r"(smem_u32(&mbars2[tid])), "r"(4u) : "memory");
  __syncthreads();

  // ---- init: alpha0 (2 batches), M0; x1 + wmxp[1] built LOCALLY ----
  float M0[2];
  {
    for (int idx = tid; idx < 2 * HH; idx += NT) {
      int bb = idx >> 9, k = idx & 511;
      a0s[idx] = __logf(gamma[k]) + __ldg(&beta[(size_t)k * VV + sids[bb][0]]);
    }
    __syncthreads();
    {
      int bb = warp >> 3, seg = warp & 7;
      float m = fmaxf(a0s[bb * 512 + seg * 64 + lane],
                      a0s[bb * 512 + seg * 64 + 32 + lane]);
      #pragma unroll
      for (int o = 16; o > 0; o >>= 1)
        m = fmaxf(m, __shfl_xor_sync(0xffffffffu, m, o));
      if (lane == 0) smax2[warp] = m;
    }
    __syncthreads();
    #pragma unroll
    for (int bb = 0; bb < 2; bb++) {
      float m = smax2[bb * 8];
      #pragma unroll
      for (int s = 1; s < 8; s++) m = fmaxf(m, smax2[bb * 8 + s]);
      M0[bb] = m;
    }
    {
      int bx = tid >> 8, kp = tid & 255;
      float v0 = __expf(a0s[bx * 512 + 2 * kp]     - M0[bx]);
      float v1 = __expf(a0s[bx * 512 + 2 * kp + 1] - M0[bx]);
      xsb[1][bx][kp] = pkbf(v0, v1);
    }
    {
      #pragma unroll
      for (int bb = 0; bb < 2; bb++) {
        float m = a0s[bb * 512 + warp * 32 + lane];
        #pragma unroll
        for (int o = 16; o > 0; o >>= 1)
          m = fmaxf(m, __shfl_xor_sync(0xffffffffu, m, o));
        if (lane == 0) wmxp[1][warp >> 2][warp & 3][bb] = __expf(m - M0[bb]);
      }
    }
    __syncthreads();
  }
  CLUSTER_SYNC();

  const bool act = (tid < 256);
  const int  b   = tid >> 7;           // batch (0/1) for act threads
  const int  r   = tid & (RPC - 1);    // row-in-slice
  const int  h   = base + r;
  const float C0 = M0[b & 1];
  int Cexp = 0;
  const u32 xsb_u  = smem_u32(xsb);
  const u32 wmxp_u = smem_u32(wmxp);
  const u32 mb0_u  = smem_u32(&mbars2[0]);
  int phs0 = 0, phs1 = 0;

  // depth-2 emission prefetch
  float e_cur = 0.0f, bq = 0.0f;
  if (act) {
    e_cur = __expf(__ldg(&beta[(size_t)h * VV + sids[b][1]]));
    bq = __ldg(&beta[(size_t)h * VV + sids[b][2]]);
  }

  for (int t = 1; t < TT; t++) {
    const int par = t & 1;

    float bnew = 0.0f;
    if (act && t + 2 < TT)
      bnew = __ldg(&beta[(size_t)h * VV + sids[b][t + 2]]);

    if (t >= 2) {
      if (par == 0) { mbar_wait_acq(mb0_u, phs0); phs0 ^= 1; }
      else          { mbar_wait_acq(mb0_u + 8, phs1); phs1 ^= 1; }
    }

    // M-fold hoisted (wmxp[par] valid post-wait; hides under MMA latency)
    float invM = 0.0f;
    int ebd = 0;
    if (act) {
      float M = wmxp[par][0][0][b];
      #pragma unroll
      for (int q = 0; q < 4; q++)
        #pragma unroll
        for (int qr = 0; qr < 4; qr++)
          M = fmaxf(M, wmxp[par][q][qr][b]);
      int eb = (int)(__float_as_uint(M) >> 23);
      invM = __uint_as_float((u32)(254 - eb) << 23);
      ebd = eb - 127;
    }

    // 16 mma.sync per warp, B fragments straight from local xsb[par]
    float c0 = 0.f, c1 = 0.f, c2 = 0.f, c3 = 0.f;
    float d0 = 0.f, d1 = 0.f, d2 = 0.f, d3 = 0.f;
    {
      const int kpb = kh * 128;
      #pragma unroll
      for (int kt = 0; kt < 16; kt += 2) {
        u32 b0 = 0, b1 = 0, b2 = 0, b3 = 0;
        if (lane < 8) {             // col = r4 (2 real batches); rest zero
          b0 = xsb[par][r4][kpb + kt * 8 + tig];
          b1 = xsb[par][r4][kpb + kt * 8 + tig + 4];
          b2 = xsb[par][r4][kpb + kt * 8 + 8 + tig];
          b3 = xsb[par][r4][kpb + kt * 8 + 8 + tig + 4];
        }
        MMA16816(c0, c1, c2, c3,
                 Areg[kt * 4 + 0], Areg[kt * 4 + 1],
                 Areg[kt * 4 + 2], Areg[kt * 4 + 3], b0, b1);
        MMA16816(d0, d1, d2, d3,
                 Areg[kt * 4 + 4], Areg[kt * 4 + 5],
                 Areg[kt * 4 + 6], Areg[kt * 4 + 7], b2, b3);
      }
    }
    if (tig == 0) {
      red2[kh][mt * 16 + r4]     = make_float2(c0 + d0, c1 + d1);
      red2[kh][mt * 16 + r4 + 8] = make_float2(c2 + d2, c3 + d3);
    }
    __syncthreads();   // red2 complete; all reads of xsb[par] done

    if (act) {
      const float* rk0 = (const float*)&red2[0][0];
      const float* rk1 = (const float*)&red2[1][0];
      float z = rk0[r * 2 + b] + rk1[r * 2 + b];

      Cexp += ebd;
      float u = z * e_cur * invM;

      if (t == TT - 1) {
        out[(cl * 2 + b) * HH + h] =
            (float)((double)__logf(u) + (double)C0
                    + (double)Cexp * 0.6931471805599453);
      } else {
        // pair-packed push to this thread's 2 target ranks (R13 transport)
        float partner = __shfl_xor_sync(0xffffffffu, u, 1);
        u32 pair = (r & 1) ? pkbf(partner, u) : pkbf(u, partner);
        u32 loff = xsb_u + (u32)((((par ^ 1) * 2 + b) * 264 + (h >> 1)) * 4);
        int rk0i = (r & 1) ? 2 : 0;
        u32 ra0 = mapa_u32(loff, rk0i);
        u32 ra1 = mapa_u32(loff, rk0i + 1);
        asm volatile("st.shared::cluster.u32 [%0], %1;" :: "r"(ra0), "r"(pair) : "memory");
        asm volatile("st.shared::cluster.u32 [%0], %1;" :: "r"(ra1), "r"(pair) : "memory");

        // warp max via redux (u > 0 => float max == uint max)
        u32 wmu;
        asm("redux.sync.max.u32 %0, %1, 0xffffffff;" : "=r"(wmu) : "r"(__float_as_uint(u)));
        if (lane < 4) {
          u32 woff = wmxp_u +
              (u32)(((((par ^ 1) * 4 + myq) * 4 + (warp & 3)) * 2 + b) * 4);
          u32 wra = mapa_u32(woff, lane);
          asm volatile("st.shared::cluster.u32 [%0], %1;" :: "r"(wra), "r"(wmu) : "memory");
        }

        e_cur = __expf(bq);
        bq = bnew;
        asm volatile("bar.sync 1, 256;" ::: "memory");   // act pushes issued
        if (warp == 0 && lane < 4) {
          u32 ra = mapa_u32(mb0_u + (u32)((par ^ 1) * 8), lane);
          asm volatile("mbarrier.arrive.release.cluster.shared::cluster.b64 _, [%0];"
                       :: "r"(ra) : "memory");
        }
      }
    }
    // warps 8-15 run ahead into the next step's wait + MMA
  }
}

extern "C" void kernel_launch(void* const* d_in, const int* in_sizes, int n_in,
                              void* d_out, int out_size) {
  const float* A     = (const float*)d_in[0];   // alpha_exp (H,H)
  const float* beta  = (const float*)d_in[1];   // (H,V)
  const float* gamma = (const float*)d_in[2];   // (1,H)
  const int*   ids   = (const int*)d_in[3];     // (B,T) int32
  float* out = (float*)d_out;                   // (B,H) f32

  hmm_main<<<128, NT>>>(A, beta, gamma, ids, out);
}